// round 1
// baseline (speedup 1.0000x reference)
#include <cuda_runtime.h>
#include <stdint.h>

#define D_DIM   256
#define TM      128
#define TN      128
#define KC      32
#define K_NN    16
#define THREADS 256

// scratch for per-row squared norms (max 128K rows)
__device__ float g_sq[1 << 17];

// ---------------------------------------------------------------------------
// Kernel 1: per-row squared norm. One warp per row.
// ---------------------------------------------------------------------------
__global__ void sqnorm_kernel(const float* __restrict__ h, int n_rows) {
    int row  = blockIdx.x * 8 + (threadIdx.x >> 5);
    int lane = threadIdx.x & 31;
    if (row >= n_rows) return;
    const float4* h4 = (const float4*)(h + (size_t)row * D_DIM);
    float s = 0.f;
#pragma unroll
    for (int p = 0; p < 2; ++p) {
        float4 v = h4[lane + 32 * p];
        s += v.x * v.x + v.y * v.y + v.z * v.z + v.w * v.w;
    }
#pragma unroll
    for (int o = 16; o > 0; o >>= 1)
        s += __shfl_xor_sync(0xffffffffu, s, o);
    if (lane == 0) g_sq[row] = s;
}

// ---------------------------------------------------------------------------
// Kernel 2: fused per-segment distance GEMM + top-16 selection.
// Grid: (L/TM, B). Block: 256 threads. 8x8 micro-tile with f32x2 packed FMA.
// ---------------------------------------------------------------------------
__global__ void __launch_bounds__(THREADS, 1)
knn_kernel(const float* __restrict__ h,
           float* __restrict__ out_d,
           float* __restrict__ out_s,
           float* __restrict__ out_t,
           int L, int write_idx) {
    extern __shared__ float sm[];
    float* As   = sm;                       // [KC][TM]   k-major
    float* Bs   = As + KC * TM;             // [KC][TN]   k-major
    float* dbuf = Bs + KC * TN;             // [TM][TN+1] distance tile
    float* sqi  = dbuf + TM * (TN + 1);     // [TM]
    float* sqj  = sqi + TM;                 // [TN]

    const int b   = blockIdx.y;
    const int i0  = blockIdx.x * TM;
    const int tid = threadIdx.x;
    const int tx  = tid & 15;               // j direction (16)
    const int ty  = tid >> 4;               // i direction (16)
    const float* hb = h + (size_t)b * L * D_DIM;

    // persistent per-row top-K state (threads 0..127 own row i0+tid)
    float heap[K_NN];
    int   hidx[K_NN];
#pragma unroll
    for (int t = 0; t < K_NN; ++t) { heap[t] = 3.4e38f; hidx[t] = 0; }

    if (tid < TM) sqi[tid] = g_sq[(size_t)b * L + i0 + tid];

    for (int jt = 0; jt < L; jt += TN) {
        __syncthreads();                    // prev selection done; safe to reuse sqj/dbuf
        if (tid < TN) sqj[tid] = g_sq[(size_t)b * L + jt + tid];

        // packed f32x2 accumulators: 8 rows x 4 column-pairs
        unsigned long long acc2[8][4];
#pragma unroll
        for (int r = 0; r < 8; ++r)
#pragma unroll
            for (int c = 0; c < 4; ++c) acc2[r][c] = 0ull;

        for (int kc = 0; kc < D_DIM; kc += KC) {
            __syncthreads();
            // stage A (i-tile) and B (j-tile) k-chunks, transposed to k-major
#pragma unroll
            for (int p = 0; p < 4; ++p) {
                int q   = tid + p * THREADS;      // 0..1023
                int row = q >> 3;                 // 0..127
                int c4  = q & 7;                  // 0..7 (float4 within 32 k)
                float4 va = *(const float4*)(hb + (size_t)(i0 + row) * D_DIM + kc + c4 * 4);
                float4 vb = *(const float4*)(hb + (size_t)(jt + row) * D_DIM + kc + c4 * 4);
                int k0 = c4 * 4;
                As[(k0 + 0) * TM + row] = va.x;
                As[(k0 + 1) * TM + row] = va.y;
                As[(k0 + 2) * TM + row] = va.z;
                As[(k0 + 3) * TM + row] = va.w;
                Bs[(k0 + 0) * TN + row] = vb.x;
                Bs[(k0 + 1) * TN + row] = vb.y;
                Bs[(k0 + 2) * TN + row] = vb.z;
                Bs[(k0 + 3) * TN + row] = vb.w;
            }
            __syncthreads();

#pragma unroll
            for (int kk = 0; kk < KC; ++kk) {
                float4 a0 = *(const float4*)&As[kk * TM + ty * 8];
                float4 a1 = *(const float4*)&As[kk * TM + ty * 8 + 4];
                float4 b0 = *(const float4*)&Bs[kk * TN + tx * 8];
                float4 b1 = *(const float4*)&Bs[kk * TN + tx * 8 + 4];
                float av[8] = {a0.x, a0.y, a0.z, a0.w, a1.x, a1.y, a1.z, a1.w};
                unsigned long long b2[4], a2[8];
                asm("mov.b64 %0, {%1, %2};" : "=l"(b2[0]) : "f"(b0.x), "f"(b0.y));
                asm("mov.b64 %0, {%1, %2};" : "=l"(b2[1]) : "f"(b0.z), "f"(b0.w));
                asm("mov.b64 %0, {%1, %2};" : "=l"(b2[2]) : "f"(b1.x), "f"(b1.y));
                asm("mov.b64 %0, {%1, %2};" : "=l"(b2[3]) : "f"(b1.z), "f"(b1.w));
#pragma unroll
                for (int r = 0; r < 8; ++r)
                    asm("mov.b64 %0, {%1, %1};" : "=l"(a2[r]) : "f"(av[r]));
#pragma unroll
                for (int r = 0; r < 8; ++r)
#pragma unroll
                    for (int c = 0; c < 4; ++c)
                        asm("fma.rn.f32x2 %0, %1, %2, %0;"
                            : "+l"(acc2[r][c]) : "l"(a2[r]), "l"(b2[c]));
            }
        }

        // epilogue: distances into padded smem tile
#pragma unroll
        for (int r = 0; r < 8; ++r) {
            int   i  = ty * 8 + r;
            float si = sqi[i];
            float* drow = &dbuf[i * (TN + 1) + tx * 8];
#pragma unroll
            for (int c = 0; c < 4; ++c) {
                float lo, hi;
                asm("mov.b64 {%0, %1}, %2;" : "=f"(lo), "=f"(hi) : "l"(acc2[r][c]));
                drow[2 * c]     = si + sqj[tx * 8 + 2 * c]     - 2.f * lo;
                drow[2 * c + 1] = si + sqj[tx * 8 + 2 * c + 1] - 2.f * hi;
            }
        }
        __syncthreads();

        // streaming top-16 (ascending j -> stable ties like lax.top_k)
        if (tid < TM) {
            const float* drow = &dbuf[tid * (TN + 1)];
            for (int j = 0; j < TN; ++j) {
                float d = drow[j];
                if (d < heap[K_NN - 1]) {
                    int jg = jt + j;
#pragma unroll
                    for (int t = K_NN - 1; t >= 1; --t) {
                        if (heap[t - 1] > d)      { heap[t] = heap[t - 1]; hidx[t] = hidx[t - 1]; }
                        else if (heap[t] > d)     { heap[t] = d;           hidx[t] = jg; }
                    }
                    if (heap[0] > d)              { heap[0] = d;           hidx[0] = jg; }
                }
            }
        }
    }

    // write results
    if (tid < TM) {
        size_t row  = (size_t)b * L + i0 + tid;
        float  srcv = (float)row;
        float* dd = out_d + row * K_NN;
#pragma unroll
        for (int t = 0; t < K_NN; ++t) dd[t] = heap[t];
        if (write_idx) {
            float* ds = out_s + row * K_NN;
            float* dt = out_t + row * K_NN;
#pragma unroll
            for (int t = 0; t < K_NN; ++t) {
                ds[t] = srcv;
                dt[t] = (float)((size_t)b * L + hidx[t]);
            }
        }
    }
}

// ---------------------------------------------------------------------------
extern "C" void kernel_launch(void* const* d_in, const int* in_sizes, int n_in,
                              void* d_out, int out_size) {
    const float* h = (const float*)d_in[0];
    int B = in_sizes[1];                    // segments (64)
    int n_rows = in_sizes[0] / D_DIM;       // 65536
    int L = n_rows / B;                     // 1024

    float* out_d = (float*)d_out;
    size_t Nd = (size_t)n_rows * K_NN;
    int three = (size_t)out_size >= 3 * Nd;
    float* out_s = three ? out_d + Nd : out_d;
    float* out_t = three ? out_d + 2 * Nd : out_d;

    size_t smem = (size_t)(KC * TM + KC * TN + TM * (TN + 1) + TM + TN) * sizeof(float);
    cudaFuncSetAttribute(knn_kernel, cudaFuncAttributeMaxDynamicSharedMemorySize, (int)smem);

    sqnorm_kernel<<<(n_rows + 7) / 8, 256>>>(h, n_rows);
    dim3 grid(L / TM, B);
    knn_kernel<<<grid, THREADS, smem>>>(h, out_d, out_s, out_t, L, three);
}

// round 2
// speedup vs baseline: 1.2067x; 1.2067x over previous
#include <cuda_runtime.h>
#include <stdint.h>

#define D_DIM   256
#define TM      128
#define TN      128
#define KCB     16          // B k-chunk
#define K_NN    16
#define THREADS 256
#define ASTR    130         // As stride (even, conflict-free)
#define BSTR    130
#define DSTR    130

__device__ float g_sq[1 << 17];

// ---------------------------------------------------------------------------
__global__ void sqnorm_kernel(const float* __restrict__ h, int n_rows) {
    int row  = blockIdx.x * 8 + (threadIdx.x >> 5);
    int lane = threadIdx.x & 31;
    if (row >= n_rows) return;
    const float4* h4 = (const float4*)(h + (size_t)row * D_DIM);
    float s = 0.f;
#pragma unroll
    for (int p = 0; p < 2; ++p) {
        float4 v = h4[lane + 32 * p];
        s += v.x * v.x + v.y * v.y + v.z * v.z + v.w * v.w;
    }
#pragma unroll
    for (int o = 16; o > 0; o >>= 1)
        s += __shfl_xor_sync(0xffffffffu, s, o);
    if (lane == 0) g_sq[row] = s;
}

// ---------------------------------------------------------------------------
// Fused per-segment distance GEMM + top-16.
// A-tile (128 x 256) fully resident in SMEM (k-major, stride 130).
// B staged in double-buffered 16-k chunks. f32x2 packed FMA.
// micro-tile: rows i = ty + 16r, cols j = 2tx + 32c (+0/1 packed)
// ---------------------------------------------------------------------------
__global__ void __launch_bounds__(THREADS, 1)
knn_kernel(const float* __restrict__ h,
           float* __restrict__ out_d,
           float* __restrict__ out_s,
           float* __restrict__ out_t,
           int L, int write_idx) {
    extern __shared__ float sm[];
    float* As   = sm;                           // [D][ASTR]
    float* Bs   = As + D_DIM * ASTR;            // 2 x [KCB][BSTR]
    float* dbuf = Bs + 2 * KCB * BSTR;          // [TM][DSTR]
    float* sqi  = dbuf + TM * DSTR;             // [TM]
    float* sqj  = sqi + TM;                     // [TN]

    const int b   = blockIdx.y;
    const int i0  = blockIdx.x * TM;
    const int tid = threadIdx.x;
    const int tx  = tid & 15;
    const int ty  = tid >> 4;
    const float* hb = h + (size_t)b * L * D_DIM;

    // ---- stage full A tile (one-time) ----
#pragma unroll
    for (int p = 0; p < 32; ++p) {
        int q   = tid + p * THREADS;            // 0..8191
        int row = q >> 6;                       // 0..127
        int f   = q & 63;                       // float4 within 256 k
        float4 v = *(const float4*)(hb + (size_t)(i0 + row) * D_DIM + f * 4);
        As[(4 * f + 0) * ASTR + row] = v.x;
        As[(4 * f + 1) * ASTR + row] = v.y;
        As[(4 * f + 2) * ASTR + row] = v.z;
        As[(4 * f + 3) * ASTR + row] = v.w;
    }
    if (tid < TM) sqi[tid] = g_sq[(size_t)b * L + i0 + tid];

    float heap[K_NN];
    int   hidx[K_NN];
#pragma unroll
    for (int t = 0; t < K_NN; ++t) { heap[t] = 3.4e38f; hidx[t] = 0; }

    for (int jt = 0; jt < L; jt += TN) {
        __syncthreads();                        // selection done; safe to reuse sqj/Bs
        if (tid < TN) sqj[tid] = g_sq[(size_t)b * L + jt + tid];

        // stage chunk 0 into buffer 0
#pragma unroll
        for (int p = 0; p < 2; ++p) {
            int q   = tid + p * THREADS;
            int row = q >> 2;
            int c4  = q & 3;
            float4 v = *(const float4*)(hb + (size_t)(jt + row) * D_DIM + c4 * 4);
            Bs[(4 * c4 + 0) * BSTR + row] = v.x;
            Bs[(4 * c4 + 1) * BSTR + row] = v.y;
            Bs[(4 * c4 + 2) * BSTR + row] = v.z;
            Bs[(4 * c4 + 3) * BSTR + row] = v.w;
        }

        unsigned long long acc2[8][4];
#pragma unroll
        for (int r = 0; r < 8; ++r)
#pragma unroll
            for (int c = 0; c < 4; ++c) acc2[r][c] = 0ull;

        __syncthreads();

#pragma unroll 1
        for (int ch = 0; ch < D_DIM / KCB; ++ch) {
            const float* Bc = Bs + (ch & 1) * (KCB * BSTR);

            // prefetch next chunk into registers (latency hidden by FMA phase)
            float4 nv0, nv1;
            if (ch < D_DIM / KCB - 1) {
                int kbase = (ch + 1) * KCB;
                {
                    int q = tid, row = q >> 2, c4 = q & 3;
                    nv0 = *(const float4*)(hb + (size_t)(jt + row) * D_DIM + kbase + c4 * 4);
                }
                {
                    int q = tid + THREADS, row = q >> 2, c4 = q & 3;
                    nv1 = *(const float4*)(hb + (size_t)(jt + row) * D_DIM + kbase + c4 * 4);
                }
            }

#pragma unroll
            for (int kk = 0; kk < KCB; ++kk) {
                const float* arow = &As[(ch * KCB + kk) * ASTR + ty];
                unsigned long long a2[8], b2[4];
#pragma unroll
                for (int r = 0; r < 8; ++r) {
                    float a = arow[16 * r];
                    asm("mov.b64 %0, {%1, %1};" : "=l"(a2[r]) : "f"(a));
                }
                const unsigned long long* bp =
                    (const unsigned long long*)&Bc[kk * BSTR + 2 * tx];
#pragma unroll
                for (int c = 0; c < 4; ++c) b2[c] = bp[16 * c];
#pragma unroll
                for (int r = 0; r < 8; ++r)
#pragma unroll
                    for (int c = 0; c < 4; ++c)
                        asm("fma.rn.f32x2 %0, %1, %2, %0;"
                            : "+l"(acc2[r][c]) : "l"(a2[r]), "l"(b2[c]));
            }

            if (ch < D_DIM / KCB - 1) {
                float* Bn = Bs + ((ch + 1) & 1) * (KCB * BSTR);
                {
                    int q = tid, row = q >> 2, c4 = q & 3;
                    Bn[(4 * c4 + 0) * BSTR + row] = nv0.x;
                    Bn[(4 * c4 + 1) * BSTR + row] = nv0.y;
                    Bn[(4 * c4 + 2) * BSTR + row] = nv0.z;
                    Bn[(4 * c4 + 3) * BSTR + row] = nv0.w;
                }
                {
                    int q = tid + THREADS, row = q >> 2, c4 = q & 3;
                    Bn[(4 * c4 + 0) * BSTR + row] = nv1.x;
                    Bn[(4 * c4 + 1) * BSTR + row] = nv1.y;
                    Bn[(4 * c4 + 2) * BSTR + row] = nv1.z;
                    Bn[(4 * c4 + 3) * BSTR + row] = nv1.w;
                }
            }
            __syncthreads();
        }

        // ---- epilogue: distances into dbuf ----
#pragma unroll
        for (int r = 0; r < 8; ++r) {
            int   i  = ty + 16 * r;
            float si = sqi[i];
            float* drow = &dbuf[i * DSTR];
#pragma unroll
            for (int c = 0; c < 4; ++c) {
                float lo, hi;
                asm("mov.b64 {%0, %1}, %2;" : "=f"(lo), "=f"(hi) : "l"(acc2[r][c]));
                int j0 = 2 * tx + 32 * c;
                drow[j0]     = si + sqj[j0]     - 2.f * lo;
                drow[j0 + 1] = si + sqj[j0 + 1] - 2.f * hi;
            }
        }
        __syncthreads();

        // ---- streaming top-16 (ascending j, tie-stable) ----
        if (tid < TM) {
            const float* drow = &dbuf[tid * DSTR];
            for (int j = 0; j < TN; ++j) {
                float d = drow[j];
                if (d < heap[K_NN - 1]) {
                    int jg = jt + j;
#pragma unroll
                    for (int t = K_NN - 1; t >= 1; --t) {
                        if (heap[t - 1] > d)  { heap[t] = heap[t - 1]; hidx[t] = hidx[t - 1]; }
                        else if (heap[t] > d) { heap[t] = d;           hidx[t] = jg; }
                    }
                    if (heap[0] > d)          { heap[0] = d;           hidx[0] = jg; }
                }
            }
        }
    }

    if (tid < TM) {
        size_t row  = (size_t)b * L + i0 + tid;
        float  srcv = (float)row;
        float* dd = out_d + row * K_NN;
#pragma unroll
        for (int t = 0; t < K_NN; ++t) dd[t] = heap[t];
        if (write_idx) {
            float* ds = out_s + row * K_NN;
            float* dt = out_t + row * K_NN;
#pragma unroll
            for (int t = 0; t < K_NN; ++t) {
                ds[t] = srcv;
                dt[t] = (float)((size_t)b * L + hidx[t]);
            }
        }
    }
}

// ---------------------------------------------------------------------------
extern "C" void kernel_launch(void* const* d_in, const int* in_sizes, int n_in,
                              void* d_out, int out_size) {
    const float* h = (const float*)d_in[0];
    int B = in_sizes[1];
    int n_rows = in_sizes[0] / D_DIM;
    int L = n_rows / B;

    float* out_d = (float*)d_out;
    size_t Nd = (size_t)n_rows * K_NN;
    int three = (size_t)out_size >= 3 * Nd;
    float* out_s = three ? out_d + Nd : out_d;
    float* out_t = three ? out_d + 2 * Nd : out_d;

    size_t smem = (size_t)(D_DIM * ASTR + 2 * KCB * BSTR + TM * DSTR + TM + TN) * sizeof(float);
    cudaFuncSetAttribute(knn_kernel, cudaFuncAttributeMaxDynamicSharedMemorySize, (int)smem);

    sqnorm_kernel<<<(n_rows + 7) / 8, 256>>>(h, n_rows);
    dim3 grid(L / TM, B);
    knn_kernel<<<grid, THREADS, smem>>>(h, out_d, out_s, out_t, L, three);
}